// round 7
// baseline (speedup 1.0000x reference)
#include <cuda_runtime.h>

// Problem shape fixed by setup_inputs(): B=16, C=1024, H=W=32, NH=16.
#define B_  16
#define C_  1024
#define H_  32
#define W_  32
#define HW_ (H_*W_)
#define NH_ 16
#define P_  (H_*W_)       // 1024
#define N_  (P_+1)        // 1025
#define K_  10

// Scratch (__device__ globals; no allocations allowed)
__device__ float          g_cls[B_][P_];        // sum over heads of cls attn
__device__ float          g_slf[B_][P_];        // sum over heads of self attn
__device__ int            g_cpos[B_][K_];       // center positions (top-k)
__device__ int            g_nbr[B_][K_][8];     // clipped neighbor positions
__device__ unsigned short g_map[B_][P_];        // 0=copy, 0x8000|slot=center, 0x4000|(slot<<3)|j=winner
__device__ float          g_w[B_][K_][8];       // softmax weights
__device__ float          g_str[B_][K_][8];     // suppression strengths

__constant__ int c_dy[8] = {-1,-1,-1, 0, 0, 1, 1, 1};
__constant__ int c_dx[8] = {-1, 0, 1,-1, 1,-1, 0, 1};

// ---------------------------------------------------------------------------
// Launch 1: zero the diag accumulator.
// ---------------------------------------------------------------------------
__global__ void init_slf_kernel() {
    g_slf[blockIdx.x][threadIdx.x] = 0.f;
}

// ---------------------------------------------------------------------------
// Launch 2: zero the fixup map.
// ---------------------------------------------------------------------------
__global__ void init_map_kernel() {
    g_map[blockIdx.x][threadIdx.x] = 0;
}

// ---------------------------------------------------------------------------
// Launch 3: cls sums. Fully coalesced row-0 reads, direct store (no atomics).
// grid = B blocks x 1024 threads; 16 independent loads per thread.
// ---------------------------------------------------------------------------
__global__ void __launch_bounds__(1024) cls_kernel(const float* __restrict__ attn) {
    int b = blockIdx.x, t = threadIdx.x;
    const float* base = attn + (size_t)b * NH_ * (size_t)N_ * N_ + 1 + t;
    float s = 0.f;
#pragma unroll
    for (int h = 0; h < NH_; h++)
        s += __ldg(base + (size_t)h * N_ * N_);
    g_cls[b][t] = s;
}

// ---------------------------------------------------------------------------
// Launch 4 (ncu-captured slot): diagonal gather, PUREST FORM.
// 262,144 threads; each thread: exactly ONE independent load + one spread
// atomic. No loops, no chained addresses. If any SM-side serialization was
// behind the ~170us, this form removes it; if DRAM random-line rate is the
// floor, this profile shows it directly.
// grid = 1024 blocks x 256 threads: block = (bh, quarter).
// ---------------------------------------------------------------------------
__global__ void __launch_bounds__(256) diag_kernel(const float* __restrict__ attn) {
    int g  = blockIdx.x;           // 0..1023
    int bh = g >> 2;               // 0..255
    int q  = g & 3;
    int p  = q * 256 + threadIdx.x;
    int b  = bh >> 4;
    float v = __ldg(attn + (size_t)bh * N_ * N_ + (size_t)(1 + p) * (N_ + 1));
    atomicAdd(&g_slf[b][p], v);
}

// ---------------------------------------------------------------------------
// Launch 5: warp-per-batch top-10 in registers, winner bitmask + fixup map.
// ratio = cls_sum / (slf_sum + 16e-8)  ==  (cls/16) / (slf/16 + 1e-8)
// ---------------------------------------------------------------------------
__global__ void topk_kernel() {
    int b = blockIdx.x;
    int lane = threadIdx.x;

    unsigned long long key[32];
#pragma unroll
    for (int u = 0; u < 32; u++) {
        int p = u * 32 + lane;
        float rt = g_cls[b][p] / (g_slf[b][p] + 1.6e-7f);
        key[u] = ((unsigned long long)__float_as_uint(rt) << 32)
               | (unsigned)(0xFFFFFFFFu - (unsigned)p);   // tie -> smaller index
    }
    int sel[K_];
#pragma unroll
    for (int k = 0; k < K_; k++) {
        unsigned long long lm = 0ull; int li = 0;
#pragma unroll
        for (int u = 0; u < 32; u++)
            if (key[u] > lm) { lm = key[u]; li = u; }
        unsigned long long wm = lm;
#pragma unroll
        for (int off = 16; off; off >>= 1) {
            unsigned long long o = __shfl_xor_sync(0xffffffffu, wm, off);
            if (o > wm) wm = o;
        }
        if (lm == wm) key[li] = 0ull;           // unique: index embedded in key
        sel[k] = (int)(0xFFFFFFFFu - (unsigned)(wm & 0xFFFFFFFFull));
    }

    if (lane == 0) {
        int rr[K_], cc[K_];
        int ny[K_][8], nx[K_][8];
#pragma unroll
        for (int i = 0; i < K_; i++) {
            g_cpos[b][i] = sel[i];
            rr[i] = sel[i] / W_; cc[i] = sel[i] % W_;
#pragma unroll
            for (int j = 0; j < 8; j++) {
                int y = rr[i] + c_dy[j]; y = y < 0 ? 0 : (y > H_ - 1 ? H_ - 1 : y);
                int x = cc[i] + c_dx[j]; x = x < 0 ? 0 : (x > W_ - 1 ? W_ - 1 : x);
                ny[i][j] = y; nx[i][j] = x;
                g_nbr[b][i][j] = y * W_ + x;
            }
        }
        // Last-writer-wins: walk slots from highest k down; first claimant of
        // a non-center position is the reference loop's last writer.
        int cy[K_ * 8], cx[K_ * 8]; int ncl = 0;
        for (int k = K_ * 8 - 1; k >= 0; k--) {
            int i = k >> 3, j = k & 7;
            int y = ny[i][j], x = nx[i][j];
            bool skip = false;
            for (int m = 0; m < K_; m++)
                if (y == rr[m] && x == cc[m]) { skip = true; break; }  // centers end as wavg
            if (skip) continue;
            for (int m = 0; m < ncl; m++)
                if (cy[m] == y && cx[m] == x) { skip = true; break; }  // later slot already wrote
            if (skip) continue;
            cy[ncl] = y; cx[ncl] = x; ncl++;
            g_map[b][y * W_ + x] = (unsigned short)(0x4000u | (i << 3) | j);
        }
        for (int i = 0; i < K_; i++)
            g_map[b][sel[i]] = (unsigned short)(0x8000u | i);
    }
}

// ---------------------------------------------------------------------------
// Launch 6: stats per (b,slot): 17 block sums -> w[8], str[8]. Read-only fm.
// ---------------------------------------------------------------------------
__global__ void __launch_bounds__(256) stats_kernel(const float* __restrict__ fm) {
    int blk = blockIdx.x;
    int b = blk / K_, i = blk % K_;
    int cpos = g_cpos[b][i];
    int np[8];
#pragma unroll
    for (int j = 0; j < 8; j++) np[j] = g_nbr[b][i][j];

    const float* f = fm + (size_t)b * C_ * HW_;
    int t = threadIdx.x;

    float dot[8] = {0,0,0,0,0,0,0,0};
    float n2[8]  = {0,0,0,0,0,0,0,0};
    float o2 = 0.f;

#pragma unroll
    for (int u = 0; u < 4; u++) {
        int ch = t + u * 256;
        const float* fc = f + (size_t)ch * HW_;
        float v = fc[cpos];
        o2 += v * v;
#pragma unroll
        for (int j = 0; j < 8; j++) {
            float nv = fc[np[j]];
            dot[j] += nv * v;
            n2[j]  += nv * nv;
        }
    }

    __shared__ float part[17][8];
    float vals[17];
    vals[0] = o2;
#pragma unroll
    for (int j = 0; j < 8; j++) { vals[1 + j] = dot[j]; vals[9 + j] = n2[j]; }
#pragma unroll
    for (int k = 0; k < 17; k++) {
        float v = vals[k];
#pragma unroll
        for (int off = 16; off; off >>= 1) v += __shfl_down_sync(0xffffffffu, v, off);
        if ((t & 31) == 0) part[k][t >> 5] = v;
    }
    __syncthreads();

    if (t == 0) {
        float sums[17];
#pragma unroll
        for (int k = 0; k < 17; k++) {
            float s = 0.f;
#pragma unroll
            for (int wrp = 0; wrp < 8; wrp++) s += part[k][wrp];
            sums[k] = s;
        }
        float on = fmaxf(sqrtf(sums[0]), 1e-12f);
        float sim[8], z[8];
        float zmax = -1e30f;
#pragma unroll
        for (int j = 0; j < 8; j++) {
            float nn = fmaxf(sqrtf(sums[9 + j]), 1e-12f);
            sim[j] = sums[1 + j] / (nn * on);
            z[j] = fmaxf(1.f - sim[j], 0.f);
            zmax = fmaxf(zmax, z[j]);
        }
        float es = 0.f, e[8];
#pragma unroll
        for (int j = 0; j < 8; j++) { e[j] = expf(z[j] - zmax); es += e[j]; }
        float inv = 1.f / es;
#pragma unroll
        for (int j = 0; j < 8; j++) {
            g_w[b][i][j]   = e[j] * inv;
            g_str[b][i][j] = fminf(fmaxf(sim[j] * 0.1f, 0.f), 1.f);
        }
    }
}

// ---------------------------------------------------------------------------
// Launch 7: fused copy + fixup. One block per (b, channel) row of 1024 floats.
// ---------------------------------------------------------------------------
__global__ void __launch_bounds__(256) apply_kernel(const float* __restrict__ fm,
                                                    float* __restrict__ out) {
    int b  = blockIdx.x >> 10;
    int ch = blockIdx.x & 1023;
    int t  = threadIdx.x;

    const float4* src = (const float4*)(fm  + ((size_t)b * C_ + ch) * HW_);
    float4*       dst = (float4*)      (out + ((size_t)b * C_ + ch) * HW_);

    __shared__ float row[P_];
    __shared__ float s_w[K_ * 8], s_str[K_ * 8];
    __shared__ int   s_nbr[K_ * 8];
    __shared__ int   s_cpos[K_];

    float4 v = src[t];
    ((float4*)row)[t] = v;
    if (t < K_ * 8) {
        s_w[t]   = ((const float*)g_w[b])[t];
        s_str[t] = ((const float*)g_str[b])[t];
        s_nbr[t] = ((const int*)g_nbr[b])[t];
        if (t < K_) s_cpos[t] = g_cpos[b][t];
    }
    __syncthreads();

    const unsigned short* mp = g_map[b] + t * 4;
    float ov[4] = {v.x, v.y, v.z, v.w};
    float res[4];
#pragma unroll
    for (int u = 0; u < 4; u++) {
        unsigned short mv = mp[u];
        float r = ov[u];
        if (mv) {
            if (mv & 0x8000u) {                     // center -> weighted avg
                int slot = mv & 0xFF;
                float acc = 0.f;
#pragma unroll
                for (int j = 0; j < 8; j++)
                    acc += s_w[slot * 8 + j] * row[s_nbr[slot * 8 + j]];
                r = acc;
            } else {                                // winner -> nbr - str*center
                int slot = (mv >> 3) & 15;
                int j    = mv & 7;
                r = r - s_str[slot * 8 + j] * row[s_cpos[slot]];
            }
        }
        res[u] = r;
    }
    dst[t] = make_float4(res[0], res[1], res[2], res[3]);
}

// ---------------------------------------------------------------------------
extern "C" void kernel_launch(void* const* d_in, const int* in_sizes, int n_in,
                              void* d_out, int out_size) {
    const float* fm   = (const float*)d_in[0];
    const float* attn = (const float*)d_in[1];
    float* out = (float*)d_out;

    init_slf_kernel<<<B_, P_>>>();          // launch 1
    init_map_kernel<<<B_, P_>>>();          // launch 2
    cls_kernel<<<B_, 1024>>>(attn);         // launch 3
    diag_kernel<<<1024, 256>>>(attn);       // launch 4  <- ncu capture slot
    topk_kernel<<<B_, 32>>>();              // launch 5
    stats_kernel<<<B_ * K_, 256>>>(fm);     // launch 6
    apply_kernel<<<B_ * C_, 256>>>(fm, out);// launch 7
}

// round 8
// speedup vs baseline: 2.9261x; 2.9261x over previous
#include <cuda_runtime.h>

// Problem shape fixed by setup_inputs(): B=16, C=1024, H=W=32, NH=16.
#define B_  16
#define C_  1024
#define H_  32
#define W_  32
#define HW_ (H_*W_)
#define NH_ 16
#define P_  (H_*W_)       // 1024
#define N_  (P_+1)        // 1025
#define K_  10

// Scratch (__device__ globals; no allocations allowed)
__device__ float          g_cls[B_][P_];        // sum over heads of cls attn
__device__ float          g_slf[B_][P_];        // sum over heads of self attn
__device__ int            g_cpos[B_][K_];       // center positions (top-k)
__device__ int            g_nbr[B_][K_][8];     // clipped neighbor positions
__device__ unsigned short g_map[B_][P_];        // 0=copy, 0x8000|slot=center, 0x4000|(slot<<3)|j=winner
__device__ float          g_w[B_][K_][8];       // softmax weights
__device__ float          g_str[B_][K_][8];     // suppression strengths

__constant__ int c_dy[8] = {-1,-1,-1, 0, 0, 1, 1, 1};
__constant__ int c_dx[8] = {-1, 0, 1,-1, 1,-1, 0, 1};

// ---------------------------------------------------------------------------
// Launch 1: cls sums (coalesced row-0 reads) + zero the diag accumulator.
// grid = B blocks x 1024 threads; 16 independent loads per thread.
// ---------------------------------------------------------------------------
__global__ void __launch_bounds__(1024) cls_kernel(const float* __restrict__ attn) {
    int b = blockIdx.x, t = threadIdx.x;
    const float* base = attn + (size_t)b * NH_ * (size_t)N_ * N_ + 1 + t;
    float s = 0.f;
#pragma unroll
    for (int h = 0; h < NH_; h++)
        s += __ldg(base + (size_t)h * N_ * N_);
    g_cls[b][t] = s;
    g_slf[b][t] = 0.f;
}

// ---------------------------------------------------------------------------
// Launch 2: diagonal gather (measured 10.5us). One load + one spread atomic
// per thread. grid = 1024 blocks x 256 threads: block = (bh, quarter).
// ---------------------------------------------------------------------------
__global__ void __launch_bounds__(256) diag_kernel(const float* __restrict__ attn) {
    int g  = blockIdx.x;           // 0..1023
    int bh = g >> 2;               // 0..255
    int q  = g & 3;
    int p  = q * 256 + threadIdx.x;
    int b  = bh >> 4;
    float v = __ldg(attn + (size_t)bh * N_ * N_ + (size_t)(1 + p) * (N_ + 1));
    atomicAdd(&g_slf[b][p], v);
}

// ---------------------------------------------------------------------------
// Launch 3: plan. Top-10 selection (warp 0, registers only, NO dynamic
// indexing -> no local-memory spill) + PARALLEL winner mask (80 threads) +
// fixup-map construction. grid = B blocks x 128 threads.
// ratio = cls_sum / (slf_sum + 16e-8)  ==  (cls/16) / (slf/16 + 1e-8)
// ---------------------------------------------------------------------------
__global__ void __launch_bounds__(128) plan_kernel() {
    int b = blockIdx.x;
    int t = threadIdx.x;

    __shared__ int sh_sel[K_];     // top-k positions
    __shared__ int sh_tgt[K_ * 8]; // clipped target per slot

    // zero this batch's fixup map (1024 entries, 128 threads x 8)
#pragma unroll
    for (int u = 0; u < 8; u++)
        g_map[b][t + u * 128] = 0;

    if (t < 32) {
        int lane = t;
        // 32 keys per lane, registers only (all indices static).
        // ratio >= 0 so float bits are monotonic as unsigned.
        unsigned long long key[32];
#pragma unroll
        for (int u = 0; u < 32; u++) {
            int p = u * 32 + lane;
            float rt = g_cls[b][p] / (g_slf[b][p] + 1.6e-7f);
            key[u] = ((unsigned long long)__float_as_uint(rt) << 32)
                   | (unsigned)(0xFFFFFFFFu - (unsigned)p);   // tie -> smaller index
        }
#pragma unroll
        for (int k = 0; k < K_; k++) {
            unsigned long long lm = 0ull;
#pragma unroll
            for (int u = 0; u < 32; u++)
                if (key[u] > lm) lm = key[u];
            unsigned long long wm = lm;
#pragma unroll
            for (int off = 16; off; off >>= 1) {
                unsigned long long o = __shfl_xor_sync(0xffffffffu, wm, off);
                if (o > wm) wm = o;
            }
            // remove selected key WITHOUT dynamic indexing (keys unique)
#pragma unroll
            for (int u = 0; u < 32; u++)
                if (key[u] == wm) key[u] = 0ull;
            if (lane == (int)k % 32) {} // no-op; keep structure simple
            if (lane == 0)
                sh_sel[k] = (int)(0xFFFFFFFFu - (unsigned)(wm & 0xFFFFFFFFull));
        }
    }
    __syncthreads();

    // Targets for all 80 slots in parallel.
    int q = -1, i = 0, j = 0;
    if (t < K_ * 8) {
        i = t >> 3; j = t & 7;
        int sel = sh_sel[i];
        int r = sel >> 5, c = sel & 31;
        int y = r + c_dy[j]; y = y < 0 ? 0 : (y > H_ - 1 ? H_ - 1 : y);
        int x = c + c_dx[j]; x = x < 0 ? 0 : (x > W_ - 1 ? W_ - 1 : x);
        q = y * W_ + x;
        sh_tgt[t] = q;
        g_nbr[b][i][j] = q;
    }
    __syncthreads();

    if (t < K_ * 8) {
        // winner iff target is not any center AND no later slot claims it
        bool center = false;
#pragma unroll
        for (int m = 0; m < K_; m++)
            if (q == sh_sel[m]) center = true;
        bool later = false;
        for (int k2 = t + 1; k2 < K_ * 8; k2++)
            if (sh_tgt[k2] == q) later = true;
        if (!center && !later)
            g_map[b][q] = (unsigned short)(0x4000u | (i << 3) | j);
    }
    __syncthreads();   // center writes must override nothing / ordering-safe

    if (t < K_) {
        int sel = sh_sel[t];
        g_cpos[b][t] = sel;
        g_map[b][sel] = (unsigned short)(0x8000u | t);
    }
}

// ---------------------------------------------------------------------------
// Launch 4: stats per (b,slot): 17 block sums -> w[8], str[8]. Read-only fm.
// ---------------------------------------------------------------------------
__global__ void __launch_bounds__(256) stats_kernel(const float* __restrict__ fm) {
    int blk = blockIdx.x;
    int b = blk / K_, i = blk % K_;
    int cpos = g_cpos[b][i];
    int np[8];
#pragma unroll
    for (int j = 0; j < 8; j++) np[j] = g_nbr[b][i][j];

    const float* f = fm + (size_t)b * C_ * HW_;
    int t = threadIdx.x;

    float dot[8] = {0,0,0,0,0,0,0,0};
    float n2[8]  = {0,0,0,0,0,0,0,0};
    float o2 = 0.f;

#pragma unroll
    for (int u = 0; u < 4; u++) {
        int ch = t + u * 256;
        const float* fc = f + (size_t)ch * HW_;
        float v = fc[cpos];
        o2 += v * v;
#pragma unroll
        for (int j = 0; j < 8; j++) {
            float nv = fc[np[j]];
            dot[j] += nv * v;
            n2[j]  += nv * nv;
        }
    }

    __shared__ float part[17][8];
    float vals[17];
    vals[0] = o2;
#pragma unroll
    for (int j = 0; j < 8; j++) { vals[1 + j] = dot[j]; vals[9 + j] = n2[j]; }
#pragma unroll
    for (int k = 0; k < 17; k++) {
        float v = vals[k];
#pragma unroll
        for (int off = 16; off; off >>= 1) v += __shfl_down_sync(0xffffffffu, v, off);
        if ((t & 31) == 0) part[k][t >> 5] = v;
    }
    __syncthreads();

    if (t == 0) {
        float sums[17];
#pragma unroll
        for (int k = 0; k < 17; k++) {
            float s = 0.f;
#pragma unroll
            for (int wrp = 0; wrp < 8; wrp++) s += part[k][wrp];
            sums[k] = s;
        }
        float on = fmaxf(sqrtf(sums[0]), 1e-12f);
        float sim[8], z[8];
        float zmax = -1e30f;
#pragma unroll
        for (int j = 0; j < 8; j++) {
            float nn = fmaxf(sqrtf(sums[9 + j]), 1e-12f);
            sim[j] = sums[1 + j] / (nn * on);
            z[j] = fmaxf(1.f - sim[j], 0.f);
            zmax = fmaxf(zmax, z[j]);
        }
        float es = 0.f, e[8];
#pragma unroll
        for (int j = 0; j < 8; j++) { e[j] = expf(z[j] - zmax); es += e[j]; }
        float inv = 1.f / es;
#pragma unroll
        for (int j = 0; j < 8; j++) {
            g_w[b][i][j]   = e[j] * inv;
            g_str[b][i][j] = fminf(fmaxf(sim[j] * 0.1f, 0.f), 1.f);
        }
    }
}

// ---------------------------------------------------------------------------
// Launch 5: fused copy + fixup. One block per (b, channel) row of 1024 floats.
// ---------------------------------------------------------------------------
__global__ void __launch_bounds__(256) apply_kernel(const float* __restrict__ fm,
                                                    float* __restrict__ out) {
    int b  = blockIdx.x >> 10;
    int ch = blockIdx.x & 1023;
    int t  = threadIdx.x;

    const float4* src = (const float4*)(fm  + ((size_t)b * C_ + ch) * HW_);
    float4*       dst = (float4*)      (out + ((size_t)b * C_ + ch) * HW_);

    __shared__ float row[P_];
    __shared__ float s_w[K_ * 8], s_str[K_ * 8];
    __shared__ int   s_nbr[K_ * 8];
    __shared__ int   s_cpos[K_];

    float4 v = src[t];
    ((float4*)row)[t] = v;
    if (t < K_ * 8) {
        s_w[t]   = ((const float*)g_w[b])[t];
        s_str[t] = ((const float*)g_str[b])[t];
        s_nbr[t] = ((const int*)g_nbr[b])[t];
        if (t < K_) s_cpos[t] = g_cpos[b][t];
    }
    __syncthreads();

    const unsigned short* mp = g_map[b] + t * 4;
    float ov[4] = {v.x, v.y, v.z, v.w};
    float res[4];
#pragma unroll
    for (int u = 0; u < 4; u++) {
        unsigned short mv = mp[u];
        float r = ov[u];
        if (mv) {
            if (mv & 0x8000u) {                     // center -> weighted avg
                int slot = mv & 0xFF;
                float acc = 0.f;
#pragma unroll
                for (int j = 0; j < 8; j++)
                    acc += s_w[slot * 8 + j] * row[s_nbr[slot * 8 + j]];
                r = acc;
            } else {                                // winner -> nbr - str*center
                int slot = (mv >> 3) & 15;
                int j    = mv & 7;
                r = r - s_str[slot * 8 + j] * row[s_cpos[slot]];
            }
        }
        res[u] = r;
    }
    dst[t] = make_float4(res[0], res[1], res[2], res[3]);
}

// ---------------------------------------------------------------------------
extern "C" void kernel_launch(void* const* d_in, const int* in_sizes, int n_in,
                              void* d_out, int out_size) {
    const float* fm   = (const float*)d_in[0];
    const float* attn = (const float*)d_in[1];
    float* out = (float*)d_out;

    cls_kernel<<<B_, 1024>>>(attn);          // launch 1 (also zeroes g_slf)
    diag_kernel<<<1024, 256>>>(attn);        // launch 2
    plan_kernel<<<B_, 128>>>();              // launch 3 (topk + mask, parallel)
    stats_kernel<<<B_ * K_, 256>>>(fm);      // launch 4
    apply_kernel<<<B_ * C_, 256>>>(fm, out); // launch 5
}